// round 1
// baseline (speedup 1.0000x reference)
#include <cuda_runtime.h>
#include <cuda_bf16.h>
#include <cstdint>

#define N_NODES 100000
#define N_EDGES 1600000
#define D_IN    64
#define D_HID   256

// Scratch (static device globals -- allocation-free at runtime)
__device__ float g_agg[(size_t)N_NODES * D_IN];   // 25.6 MB
__device__ float g_h1 [(size_t)N_NODES * D_HID];  // 102.4 MB

// ---------------------------------------------------------------------------
// Kernel 1: agg[i] = eps[0] * x[i]   (fused self-term init)
// ---------------------------------------------------------------------------
__global__ void init_agg_kernel(const float* __restrict__ x,
                                const float* __restrict__ eps) {
    const float e = eps[0];
    size_t i = (size_t)blockIdx.x * blockDim.x + threadIdx.x;  // float4 index
    const float4* x4 = (const float4*)x;
    float4* a4 = (float4*)g_agg;
    float4 v = x4[i];
    v.x *= e; v.y *= e; v.z *= e; v.w *= e;
    a4[i] = v;
}

// ---------------------------------------------------------------------------
// Kernel 2: edge scatter-add. 16 lanes per edge, each lane owns one float4
// of the 64-float feature row. Vector red.global.add.v4.f32 (sm_90+).
// ---------------------------------------------------------------------------
__global__ void scatter_kernel(const float* __restrict__ x,
                               const int* __restrict__ edge_index) {
    size_t g = (size_t)blockIdx.x * blockDim.x + threadIdx.x;
    int e    = (int)(g >> 4);
    int lane = (int)(g & 15);
    int src = edge_index[e];
    int dst = edge_index[N_EDGES + e];

    const float4* x4 = (const float4*)x;
    float4 v = x4[(size_t)src * 16 + lane];

    float* p = &g_agg[(size_t)dst * D_IN + lane * 4];
    asm volatile("red.global.add.v4.f32 [%0], {%1, %2, %3, %4};"
                 :: "l"(p), "f"(v.x), "f"(v.y), "f"(v.z), "f"(v.w)
                 : "memory");
}

// ---------------------------------------------------------------------------
// Kernel 3/4: tiled GEMM  C[M,N] = op(A[M,K] @ B[K,N] + bias), op = relu?
// BM=BN=BK=64, 256 threads, 4x4 register tile per thread.
// ---------------------------------------------------------------------------
#define BM 64
#define BN 64
#define BK 64

template<int RELU>
__global__ void gemm_bias_kernel(const float* __restrict__ A,
                                 const float* __restrict__ B,
                                 const float* __restrict__ bias,
                                 float* __restrict__ C,
                                 int M, int N, int K) {
    __shared__ float As[BM][BK];   // 16 KB
    __shared__ float Bs[BK][BN];   // 16 KB

    const int tid = threadIdx.x;
    const int tx  = tid & 15;      // 0..15  -> col group (4 cols each)
    const int ty  = tid >> 4;      // 0..15  -> row group (4 rows each)
    const int row0 = blockIdx.x * BM;
    const int col0 = blockIdx.y * BN;

    float acc[4][4];
#pragma unroll
    for (int i = 0; i < 4; i++)
#pragma unroll
        for (int j = 0; j < 4; j++) acc[i][j] = 0.0f;

    for (int k0 = 0; k0 < K; k0 += BK) {
        // Load A tile (64x64) as float4s, row-major, conflict-free stores
#pragma unroll
        for (int i = 0; i < 4; i++) {
            int idx = i * 256 + tid;        // float4 index in tile (0..1023)
            int m   = idx >> 4;             // 0..63
            int kv  = (idx & 15) << 2;      // 0,4,...,60
            int grow = row0 + m;
            float4 v;
            if (grow < M) v = *(const float4*)&A[(size_t)grow * K + k0 + kv];
            else          v = make_float4(0.f, 0.f, 0.f, 0.f);
            *(float4*)&As[m][kv] = v;
        }
        // Load B tile (64x64)
#pragma unroll
        for (int i = 0; i < 4; i++) {
            int idx = i * 256 + tid;
            int kk  = idx >> 4;
            int nv  = (idx & 15) << 2;
            float4 v = *(const float4*)&B[(size_t)(k0 + kk) * N + col0 + nv];
            *(float4*)&Bs[kk][nv] = v;
        }
        __syncthreads();

#pragma unroll
        for (int k = 0; k < BK; k++) {
            float b[4];
            *(float4*)b = *(const float4*)&Bs[k][tx << 2];
            float a[4];
#pragma unroll
            for (int i = 0; i < 4; i++) a[i] = As[(ty << 2) + i][k];
#pragma unroll
            for (int i = 0; i < 4; i++)
#pragma unroll
                for (int j = 0; j < 4; j++)
                    acc[i][j] = fmaf(a[i], b[j], acc[i][j]);
        }
        __syncthreads();
    }

    // Epilogue
    float4 bb = *(const float4*)&bias[col0 + (tx << 2)];
#pragma unroll
    for (int i = 0; i < 4; i++) {
        int grow = row0 + (ty << 2) + i;
        if (grow < M) {
            float4 o;
            o.x = acc[i][0] + bb.x;
            o.y = acc[i][1] + bb.y;
            o.z = acc[i][2] + bb.z;
            o.w = acc[i][3] + bb.w;
            if (RELU) {
                o.x = fmaxf(o.x, 0.f); o.y = fmaxf(o.y, 0.f);
                o.z = fmaxf(o.z, 0.f); o.w = fmaxf(o.w, 0.f);
            }
            *(float4*)&C[(size_t)grow * N + col0 + (tx << 2)] = o;
        }
    }
}

// ---------------------------------------------------------------------------
// Launch
// inputs (metadata order): x, eps, W1, b1, W2, b2, edge_index
// ---------------------------------------------------------------------------
extern "C" void kernel_launch(void* const* d_in, const int* in_sizes, int n_in,
                              void* d_out, int out_size) {
    const float* x   = (const float*)d_in[0];
    const float* eps = (const float*)d_in[1];
    const float* W1  = (const float*)d_in[2];
    const float* b1  = (const float*)d_in[3];
    const float* W2  = (const float*)d_in[4];
    const float* b2  = (const float*)d_in[5];
    const int* edge_index = (const int*)d_in[6];
    float* out = (float*)d_out;

    float* agg; cudaGetSymbolAddress((void**)&agg, g_agg);
    float* h1;  cudaGetSymbolAddress((void**)&h1,  g_h1);

    // 1) agg = eps * x   (1.6M float4s)
    {
        int total4 = N_NODES * D_IN / 4;      // 1,600,000
        init_agg_kernel<<<total4 / 256, 256>>>(x, eps);
    }
    // 2) agg[dst] += x[src] over edges (16 lanes/edge)
    {
        size_t total = (size_t)N_EDGES * 16;  // 25,600,000
        scatter_kernel<<<(unsigned)(total / 256), 256>>>(x, edge_index);
    }
    // 3) h1 = relu(agg @ W1 + b1)   M=100000 K=64 N=256
    {
        dim3 grid((N_NODES + BM - 1) / BM, D_HID / BN);
        gemm_bias_kernel<1><<<grid, 256>>>(agg, W1, b1, h1, N_NODES, D_HID, D_IN);
    }
    // 4) out = h1 @ W2 + b2        M=100000 K=256 N=64
    {
        dim3 grid((N_NODES + BM - 1) / BM, D_IN / BN);
        gemm_bias_kernel<0><<<grid, 256>>>(h1, W2, b2, out, N_NODES, D_IN, D_HID);
    }
}

// round 4
// speedup vs baseline: 1.0722x; 1.0722x over previous
#include <cuda_runtime.h>
#include <cuda_bf16.h>
#include <cstdint>

#define N_NODES 100000
#define N_EDGES 1600000
#define D_IN    64
#define D_HID   256

// Scratch (static device globals -- allocation-free at runtime)
__device__ float g_agg[(size_t)N_NODES * D_IN];   // 25.6 MB
__device__ float g_h1 [(size_t)N_NODES * D_HID];  // 102.4 MB

// ---------------------------------------------------------------------------
// Kernel 1: agg[i] = eps[0] * x[i]   (fused self-term init)
// ---------------------------------------------------------------------------
__global__ void init_agg_kernel(const float* __restrict__ x,
                                const float* __restrict__ eps) {
    const float e = eps[0];
    size_t i = (size_t)blockIdx.x * blockDim.x + threadIdx.x;  // float4 index
    const float4* x4 = (const float4*)x;
    float4* a4 = (float4*)g_agg;
    float4 v = x4[i];
    v.x *= e; v.y *= e; v.z *= e; v.w *= e;
    a4[i] = v;
}

// ---------------------------------------------------------------------------
// Kernel 2: edge scatter-add. 16 lanes per edge, each lane owns one float4
// of the 64-float feature row. Vector red.global.add.v4.f32.
// ---------------------------------------------------------------------------
__global__ void scatter_kernel(const float* __restrict__ x,
                               const int* __restrict__ edge_index) {
    size_t g = (size_t)blockIdx.x * blockDim.x + threadIdx.x;
    int e    = (int)(g >> 4);
    int lane = (int)(g & 15);
    int src = edge_index[e];
    int dst = edge_index[N_EDGES + e];

    const float4* x4 = (const float4*)x;
    float4 v = x4[(size_t)src * 16 + lane];

    float* p = &g_agg[(size_t)dst * D_IN + lane * 4];
    asm volatile("red.global.add.v4.f32 [%0], {%1, %2, %3, %4};"
                 :: "l"(p), "f"(v.x), "f"(v.y), "f"(v.z), "f"(v.w)
                 : "memory");
}

// ---------------------------------------------------------------------------
// Kernel 3/4: tiled GEMM  C[M,N] = op(A[M,K] @ B[K,N] + bias)
// BM=128, BN=64, BK=32. 256 threads, 8x4 register tile per thread.
// A tile stored TRANSPOSED in smem; APAD=4 keeps row pitch 16B-aligned
// (132 floats = 528 B) so mainloop LDS.128 is legal.
// Smem: 32*132*4 + 32*64*4 = 24.9 KB (fits static 48 KB cap).
// ---------------------------------------------------------------------------
#define BM 128
#define BN 64
#define BK 32
#define APAD 4      // pitch = 132 floats = 528 B: 16B-aligned, offsets banks by 4

template<int RELU>
__global__ __launch_bounds__(256, 3)
void gemm_bias_kernel(const float* __restrict__ A,
                      const float* __restrict__ B,
                      const float* __restrict__ bias,
                      float* __restrict__ C,
                      int M, int N, int K) {
    __shared__ float As_T[BK][BM + APAD];   // [k][m], 16.9 KB
    __shared__ float Bs[BK][BN];            // [k][n], 8 KB

    const int tid = threadIdx.x;
    const int tx  = tid & 15;      // 0..15 -> col group (4 cols)
    const int ty  = tid >> 4;      // 0..15 -> row group (8 rows)
    const int row0 = blockIdx.x * BM;
    const int col0 = blockIdx.y * BN;

    float acc[8][4];
#pragma unroll
    for (int i = 0; i < 8; i++)
#pragma unroll
        for (int j = 0; j < 4; j++) acc[i][j] = 0.0f;

    for (int k0 = 0; k0 < K; k0 += BK) {
        // --- Load A tile (128x32) -> transposed smem ---
        // 1024 float4s, 4 per thread. m = idx>>3, kv = (idx&7)*4
#pragma unroll
        for (int i = 0; i < 4; i++) {
            int idx = i * 256 + tid;
            int m   = idx >> 3;             // 0..127
            int kv  = (idx & 7) << 2;       // 0,4,...,28
            int grow = row0 + m;
            float4 v;
            if (grow < M) v = *(const float4*)&A[(size_t)grow * K + k0 + kv];
            else          v = make_float4(0.f, 0.f, 0.f, 0.f);
            As_T[kv + 0][m] = v.x;
            As_T[kv + 1][m] = v.y;
            As_T[kv + 2][m] = v.z;
            As_T[kv + 3][m] = v.w;
        }
        // --- Load B tile (32x64), 512 float4s, 2 per thread ---
#pragma unroll
        for (int i = 0; i < 2; i++) {
            int idx = i * 256 + tid;
            int kk  = idx >> 4;             // 0..31
            int nv  = (idx & 15) << 2;      // 0..60
            *(float4*)&Bs[kk][nv] = *(const float4*)&B[(size_t)(k0 + kk) * N + col0 + nv];
        }
        __syncthreads();

        // --- Mainloop: per k, 3x LDS.128 + 32 FFMA ---
#pragma unroll
        for (int k = 0; k < BK; k++) {
            float4 a0 = *(const float4*)&As_T[k][ty * 8];
            float4 a1 = *(const float4*)&As_T[k][ty * 8 + 4];
            float4 b  = *(const float4*)&Bs[k][tx * 4];
            float a[8] = {a0.x, a0.y, a0.z, a0.w, a1.x, a1.y, a1.z, a1.w};
            float bb[4] = {b.x, b.y, b.z, b.w};
#pragma unroll
            for (int i = 0; i < 8; i++)
#pragma unroll
                for (int j = 0; j < 4; j++)
                    acc[i][j] = fmaf(a[i], bb[j], acc[i][j]);
        }
        __syncthreads();
    }

    // --- Epilogue ---
    float4 bv = *(const float4*)&bias[col0 + (tx << 2)];
#pragma unroll
    for (int i = 0; i < 8; i++) {
        int grow = row0 + ty * 8 + i;
        if (grow < M) {
            float4 o;
            o.x = acc[i][0] + bv.x;
            o.y = acc[i][1] + bv.y;
            o.z = acc[i][2] + bv.z;
            o.w = acc[i][3] + bv.w;
            if (RELU) {
                o.x = fmaxf(o.x, 0.f); o.y = fmaxf(o.y, 0.f);
                o.z = fmaxf(o.z, 0.f); o.w = fmaxf(o.w, 0.f);
            }
            *(float4*)&C[(size_t)grow * N + col0 + (tx << 2)] = o;
        }
    }
}

// ---------------------------------------------------------------------------
// Launch.  inputs (metadata order): x, eps, W1, b1, W2, b2, edge_index
// ---------------------------------------------------------------------------
extern "C" void kernel_launch(void* const* d_in, const int* in_sizes, int n_in,
                              void* d_out, int out_size) {
    const float* x   = (const float*)d_in[0];
    const float* eps = (const float*)d_in[1];
    const float* W1  = (const float*)d_in[2];
    const float* b1  = (const float*)d_in[3];
    const float* W2  = (const float*)d_in[4];
    const float* b2  = (const float*)d_in[5];
    const int* edge_index = (const int*)d_in[6];
    float* out = (float*)d_out;

    float* agg; cudaGetSymbolAddress((void**)&agg, g_agg);
    float* h1;  cudaGetSymbolAddress((void**)&h1,  g_h1);

    // 1) agg = eps * x
    {
        int total4 = N_NODES * D_IN / 4;      // 1,600,000
        init_agg_kernel<<<total4 / 256, 256>>>(x, eps);
    }
    // 2) agg[dst] += x[src]
    {
        size_t total = (size_t)N_EDGES * 16;  // 25,600,000
        scatter_kernel<<<(unsigned)(total / 256), 256>>>(x, edge_index);
    }
    // 3) h1 = relu(agg @ W1 + b1)   M=100000 K=64 N=256
    {
        dim3 grid((N_NODES + BM - 1) / BM, D_HID / BN);
        gemm_bias_kernel<1><<<grid, 256>>>(agg, W1, b1, h1, N_NODES, D_HID, D_IN);
    }
    // 4) out = h1 @ W2 + b2         M=100000 K=256 N=64
    {
        dim3 grid((N_NODES + BM - 1) / BM, D_IN / BN);
        gemm_bias_kernel<0><<<grid, 256>>>(h1, W2, b2, out, N_NODES, D_IN, D_HID);
    }
}